// round 11
// baseline (speedup 1.0000x reference)
#include <cuda_runtime.h>
#include <cuda_bf16.h>
#include <math.h>
#include <stdint.h>

// Problem constants
#define BB 64
#define TT 512
#define DD 512
#define HH 8
#define DHH 64

// ---------------- scratch (device globals; allocation-free) ----------------
__device__ float g_qin[BB * TT * DD];
__device__ float g_kin[BB * TT * DD];
__device__ float g_qp [BB * TT * DD];
__device__ float g_kp [BB * TT * DD];
__device__ float g_vp [BB * TT * DD];
__device__ float g_res[BB * TT * DD];
__device__ float g_hid[BB * TT * 4 * DD];
__device__ float g_res2[BB * TT * DD];
// tf32-rounded weight copies
__device__ float g_wq[DD * DD];
__device__ float g_wk[DD * DD];
__device__ float g_wv[DD * DD];
__device__ float g_f1[DD * 4 * DD];
__device__ float g_f2[4 * DD * DD];

__device__ __forceinline__ uint32_t f2tf32(float x) {
    uint32_t r;
    asm("cvt.rna.tf32.f32 %0, %1;" : "=r"(r) : "f"(x));
    return r;
}
__device__ __forceinline__ float tf32r(float x) {
    return __uint_as_float(f2tf32(x));
}

#define CPASYNC16(dst, src) \
    asm volatile("cp.async.cg.shared.global [%0], [%1], 16;" :: "r"(dst), "l"(src))

// ---------------- kernel 0: round all weights to tf32 (single launch) ----------------
__global__ void roundw_all_kernel(const float* __restrict__ wq0, float* __restrict__ wq1,
                                  const float* __restrict__ wk0, float* __restrict__ wk1,
                                  const float* __restrict__ wv0, float* __restrict__ wv1,
                                  const float* __restrict__ f10, float* __restrict__ f11,
                                  const float* __restrict__ f20, float* __restrict__ f21) {
    int i = blockIdx.x * blockDim.x + threadIdx.x;
    if (i < DD * DD) {
        wq1[i] = tf32r(wq0[i]);
        wk1[i] = tf32r(wk0[i]);
        wv1[i] = tf32r(wv0[i]);
    }
    if (i < DD * 4 * DD) {
        f11[i] = tf32r(f10[i]);
        f21[i] = tf32r(f20[i]);
    }
}

// ---------------- kernel 1: positional encoding add (tf32-rounded out) ----------------
__global__ void addpe_kernel(const float* __restrict__ q, const float* __restrict__ k,
                             float* __restrict__ qo, float* __restrict__ ko) {
    int idx = blockIdx.x * blockDim.x + threadIdx.x;
    if (idx >= BB * TT * DD) return;
    int d = idx % DD;
    int t = (idx / DD) % TT;
    int j = (d < DD / 2) ? d : d - DD / 2;
    float invf = expf(-(2.0f * (float)j / (float)DD) * 9.210340371976184f); // ln(10000)
    float arg = (float)t * invf;
    float pe = (d < DD / 2) ? cosf(arg) : sinf(arg);
    qo[idx] = tf32r(q[idx] + pe);
    ko[idx] = tf32r(k[idx] + pe);
}

// ---------------- TF32 GEMM v6: 128-thread CTA, 128x64 tile, 4 CTAs/SM ----------------
// Warp grid 2x2, warp tile 64x32. 2-stage cp.async, ldmatrix A, conflict-free B.
template<bool RELU, bool ADD, bool TFOUT>
__global__ __launch_bounds__(128, 4) void tf32_gemm_v6(
        const float* __restrict__ A, const float* __restrict__ W,
        const float* __restrict__ Src, float* __restrict__ C,
        int M, int N, int K) {
    const int BK = 32;
    const int AST = 36, BST = 68;             // u32 strides; both conflict-free
    const int ASTAGE = 128 * AST, BSTAGE = 32 * BST;
    const int STAGE = ASTAGE + BSTAGE;        // 6784 u32 per stage
    extern __shared__ uint32_t sm[];

    int tid = threadIdx.x;
    int lane = tid & 31, warp = tid >> 5;     // 4 warps
    int wr = (warp >> 1) * 64;                // 2 warp-rows
    int wc = (warp & 1) * 32;                 // 2 warp-cols
    int bm = blockIdx.y * 128, bn = blockIdx.x * 64;
    int g = lane >> 2, q = lane & 3;

    uint32_t smem_base = (uint32_t)__cvta_generic_to_shared(sm);

    int lrow = ((lane >> 3) & 1) * 8 + (lane & 7);
    int lcol = (lane >> 4) * 4;

    float acc[4][4][4];
    #pragma unroll
    for (int mi = 0; mi < 4; mi++)
        #pragma unroll
        for (int ni = 0; ni < 4; ni++)
            #pragma unroll
            for (int r = 0; r < 4; r++) acc[mi][ni][r] = 0.0f;

    auto stage_load = [&](int k0, int s) {
        uint32_t abase = smem_base + (uint32_t)(s * STAGE) * 4u;
        uint32_t bbase = abase + (uint32_t)ASTAGE * 4u;
        #pragma unroll
        for (int i = 0; i < 8; i++) {
            int c = tid + i * 128;
            int row = c >> 3, col = (c & 7) * 4;
            CPASYNC16(abase + (uint32_t)(row * AST + col) * 4u,
                      A + (size_t)(bm + row) * K + k0 + col);
        }
        #pragma unroll
        for (int i = 0; i < 4; i++) {
            int c = tid + i * 128;
            int kr = c >> 4, col = (c & 15) * 4;
            CPASYNC16(bbase + (uint32_t)(kr * BST + col) * 4u,
                      W + (size_t)(k0 + kr) * N + bn + col);
        }
        asm volatile("cp.async.commit_group;");
    };

    int nk = K / BK;
    stage_load(0, 0);

    for (int it = 0; it < nk; it++) {
        if (it + 1 < nk) {
            stage_load((it + 1) * BK, (it + 1) & 1);
            asm volatile("cp.async.wait_group 1;");
        } else {
            asm volatile("cp.async.wait_group 0;");
        }
        __syncthreads();

        int s = it & 1;
        uint32_t abuf = smem_base + (uint32_t)(s * STAGE) * 4u;
        const uint32_t* Bb = sm + s * STAGE + ASTAGE;
        #pragma unroll
        for (int kk = 0; kk < BK; kk += 8) {
            uint32_t af[4][4];
            #pragma unroll
            for (int mi = 0; mi < 4; mi++) {
                uint32_t addr = abuf +
                    (uint32_t)((wr + mi * 16 + lrow) * AST + kk + lcol) * 4u;
                asm volatile(
                    "ldmatrix.sync.aligned.m8n8.x4.shared.b16 {%0,%1,%2,%3}, [%4];"
                    : "=r"(af[mi][0]), "=r"(af[mi][1]),
                      "=r"(af[mi][2]), "=r"(af[mi][3])
                    : "r"(addr));
            }
            uint32_t bf[4][2];
            #pragma unroll
            for (int ni = 0; ni < 4; ni++) {
                int cn = wc + ni * 8 + g;
                bf[ni][0] = Bb[(kk + q) * BST + cn];
                bf[ni][1] = Bb[(kk + 4 + q) * BST + cn];
            }
            #pragma unroll
            for (int mi = 0; mi < 4; mi++)
                #pragma unroll
                for (int ni = 0; ni < 4; ni++) {
                    asm volatile(
                        "mma.sync.aligned.m16n8k8.row.col.f32.tf32.tf32.f32 "
                        "{%0,%1,%2,%3},{%4,%5,%6,%7},{%8,%9},{%0,%1,%2,%3};"
                        : "+f"(acc[mi][ni][0]), "+f"(acc[mi][ni][1]),
                          "+f"(acc[mi][ni][2]), "+f"(acc[mi][ni][3])
                        : "r"(af[mi][0]), "r"(af[mi][1]), "r"(af[mi][2]), "r"(af[mi][3]),
                          "r"(bf[ni][0]), "r"(bf[ni][1]));
                }
        }
        __syncthreads();
    }

    #pragma unroll
    for (int mi = 0; mi < 4; mi++) {
        #pragma unroll
        for (int ni = 0; ni < 4; ni++) {
            int r0 = bm + wr + mi * 16 + g;
            int cn = bn + wc + ni * 8 + 2 * q;
            float v0 = acc[mi][ni][0], v1 = acc[mi][ni][1];
            float v2 = acc[mi][ni][2], v3 = acc[mi][ni][3];
            if (RELU) {
                v0 = fmaxf(v0, 0.0f); v1 = fmaxf(v1, 0.0f);
                v2 = fmaxf(v2, 0.0f); v3 = fmaxf(v3, 0.0f);
            }
            if (ADD) {
                float2 s0 = *(const float2*)(Src + (size_t)r0 * N + cn);
                float2 s1 = *(const float2*)(Src + (size_t)(r0 + 8) * N + cn);
                v0 += s0.x; v1 += s0.y; v2 += s1.x; v3 += s1.y;
            }
            if (TFOUT) {
                v0 = tf32r(v0); v1 = tf32r(v1); v2 = tf32r(v2); v3 = tf32r(v3);
            }
            *(float2*)(C + (size_t)r0 * N + cn)       = make_float2(v0, v1);
            *(float2*)(C + (size_t)(r0 + 8) * N + cn) = make_float2(v2, v3);
        }
    }
}

// ---------------- kernel 3: tf32 flash attention + residual ----------------
#define SC 64
__global__ __launch_bounds__(256) void attn_mma_kernel(
        const float* __restrict__ qp, const float* __restrict__ kp,
        const float* __restrict__ vp, const float* __restrict__ qin,
        const int* __restrict__ qlens, const int* __restrict__ klens,
        float* __restrict__ res) {
    __shared__ uint32_t Ks[SC][68];
    __shared__ uint32_t Vs[SC][72];

    int b = blockIdx.z, h = blockIdx.y;
    int t0 = blockIdx.x * 128;
    int tid = threadIdx.x, lane = tid & 31, warp = tid >> 5;
    int g = lane >> 2, q = lane & 3;
    int klen = klens[b];
    int qlen = qlens[b];
    size_t base = ((size_t)b * TT) * DD + h * DHH;
    int rbase = t0 + warp * 16;

    float O[8][4];
    #pragma unroll
    for (int ni = 0; ni < 8; ni++)
        #pragma unroll
        for (int r = 0; r < 4; r++) O[ni][r] = 0.0f;
    float l0 = 0.0f, l1 = 0.0f;

    if (t0 < qlen) {
        uint32_t aQ[8][4];
        {
            const float* q0 = qp + base + (size_t)(rbase + g) * DD;
            const float* q8 = qp + base + (size_t)(rbase + g + 8) * DD;
            #pragma unroll
            for (int kk = 0; kk < 8; kk++) {
                int c = kk * 8 + q;
                aQ[kk][0] = f2tf32(q0[c] * 0.125f);
                aQ[kk][1] = f2tf32(q8[c] * 0.125f);
                aQ[kk][2] = f2tf32(q0[c + 4] * 0.125f);
                aQ[kk][3] = f2tf32(q8[c + 4] * 0.125f);
            }
        }

        float m0 = -1e30f, m1 = -1e30f;
        int nchunks = (klen + SC - 1) / SC;

        for (int ch = 0; ch < nchunks; ch++) {
            int s0 = ch * SC;
            __syncthreads();
            #pragma unroll
            for (int i = 0; i < 4; i++) {
                int c = tid + i * 256;
                int row = c >> 4;
                int col = (c & 15) * 4;
                size_t off = base + (size_t)(s0 + row) * DD + col;
                float4 kv4 = *(const float4*)(kp + off);
                Ks[row][col + 0] = __float_as_uint(kv4.x);
                Ks[row][col + 1] = __float_as_uint(kv4.y);
                Ks[row][col + 2] = __float_as_uint(kv4.z);
                Ks[row][col + 3] = __float_as_uint(kv4.w);
                float4 vv4 = *(const float4*)(vp + off);
                Vs[row][col + 0] = __float_as_uint(vv4.x);
                Vs[row][col + 1] = __float_as_uint(vv4.y);
                Vs[row][col + 2] = __float_as_uint(vv4.z);
                Vs[row][col + 3] = __float_as_uint(vv4.w);
            }
            __syncthreads();

            float sacc[8][4];
            #pragma unroll
            for (int ni = 0; ni < 8; ni++)
                #pragma unroll
                for (int r = 0; r < 4; r++) sacc[ni][r] = 0.0f;
            #pragma unroll
            for (int kk = 0; kk < 8; kk++) {
                #pragma unroll
                for (int ni = 0; ni < 8; ni++) {
                    uint32_t b0 = Ks[ni * 8 + g][kk * 8 + q];
                    uint32_t b1 = Ks[ni * 8 + g][kk * 8 + q + 4];
                    asm volatile(
                        "mma.sync.aligned.m16n8k8.row.col.f32.tf32.tf32.f32 "
                        "{%0,%1,%2,%3},{%4,%5,%6,%7},{%8,%9},{%0,%1,%2,%3};"
                        : "+f"(sacc[ni][0]), "+f"(sacc[ni][1]),
                          "+f"(sacc[ni][2]), "+f"(sacc[ni][3])
                        : "r"(aQ[kk][0]), "r"(aQ[kk][1]), "r"(aQ[kk][2]), "r"(aQ[kk][3]),
                          "r"(b0), "r"(b1));
                }
            }

            int cb = s0 + 2 * q;
            #pragma unroll
            for (int ni = 0; ni < 8; ni++) {
                if (cb + ni * 8     >= klen) { sacc[ni][0] = -1e30f; sacc[ni][2] = -1e30f; }
                if (cb + ni * 8 + 1 >= klen) { sacc[ni][1] = -1e30f; sacc[ni][3] = -1e30f; }
            }

            float mc0 = -1e30f, mc1 = -1e30f;
            #pragma unroll
            for (int ni = 0; ni < 8; ni++) {
                mc0 = fmaxf(mc0, fmaxf(sacc[ni][0], sacc[ni][1]));
                mc1 = fmaxf(mc1, fmaxf(sacc[ni][2], sacc[ni][3]));
            }
            #pragma unroll
            for (int o = 1; o <= 2; o <<= 1) {
                mc0 = fmaxf(mc0, __shfl_xor_sync(0xffffffffu, mc0, o));
                mc1 = fmaxf(mc1, __shfl_xor_sync(0xffffffffu, mc1, o));
            }
            float mn0 = fmaxf(m0, mc0), mn1 = fmaxf(m1, mc1);
            float al0 = __expf(m0 - mn0), al1 = __expf(m1 - mn1);
            m0 = mn0; m1 = mn1;

            float rs0 = 0.0f, rs1 = 0.0f;
            #pragma unroll
            for (int ni = 0; ni < 8; ni++) {
                float p0 = __expf(sacc[ni][0] - m0);
                float p1 = __expf(sacc[ni][1] - m0);
                float p2 = __expf(sacc[ni][2] - m1);
                float p3 = __expf(sacc[ni][3] - m1);
                rs0 += p0 + p1; rs1 += p2 + p3;
                sacc[ni][0] = p0; sacc[ni][1] = p1; sacc[ni][2] = p2; sacc[ni][3] = p3;
            }
            #pragma unroll
            for (int o = 1; o <= 2; o <<= 1) {
                rs0 += __shfl_xor_sync(0xffffffffu, rs0, o);
                rs1 += __shfl_xor_sync(0xffffffffu, rs1, o);
            }
            l0 = l0 * al0 + rs0;
            l1 = l1 * al1 + rs1;
            #pragma unroll
            for (int ni = 0; ni < 8; ni++) {
                O[ni][0] *= al0; O[ni][1] *= al0;
                O[ni][2] *= al1; O[ni][3] *= al1;
            }

            int srcA = g * 4 + (q >> 1);
            int srcB = srcA + 2;
            bool odd = (q & 1);
            #pragma unroll
            for (int ks = 0; ks < 8; ks++) {
                float v00 = __shfl_sync(0xffffffffu, sacc[ks][0], srcA);
                float v01 = __shfl_sync(0xffffffffu, sacc[ks][1], srcA);
                float v10 = __shfl_sync(0xffffffffu, sacc[ks][2], srcA);
                float v11 = __shfl_sync(0xffffffffu, sacc[ks][3], srcA);
                float w00 = __shfl_sync(0xffffffffu, sacc[ks][0], srcB);
                float w01 = __shfl_sync(0xffffffffu, sacc[ks][1], srcB);
                float w10 = __shfl_sync(0xffffffffu, sacc[ks][2], srcB);
                float w11 = __shfl_sync(0xffffffffu, sacc[ks][3], srcB);
                uint32_t a0 = f2tf32(odd ? v01 : v00);
                uint32_t a1 = f2tf32(odd ? v11 : v10);
                uint32_t a2 = f2tf32(odd ? w01 : w00);
                uint32_t a3 = f2tf32(odd ? w11 : w10);
                #pragma unroll
                for (int ni = 0; ni < 8; ni++) {
                    uint32_t b0 = Vs[ks * 8 + q    ][ni * 8 + g];
                    uint32_t b1 = Vs[ks * 8 + q + 4][ni * 8 + g];
                    asm volatile(
                        "mma.sync.aligned.m16n8k8.row.col.f32.tf32.tf32.f32 "
                        "{%0,%1,%2,%3},{%4,%5,%6,%7},{%8,%9},{%0,%1,%2,%3};"
                        : "+f"(O[ni][0]), "+f"(O[ni][1]),
                          "+f"(O[ni][2]), "+f"(O[ni][3])
                        : "r"(a0), "r"(a1), "r"(a2), "r"(a3),
                          "r"(b0), "r"(b1));
                }
            }
        }
    }

    float inv0 = (l0 > 0.0f) ? 1.0f / l0 : 0.0f;
    float inv1 = (l1 > 0.0f) ? 1.0f / l1 : 0.0f;
    int r0 = rbase + g, r1 = rbase + g + 8;
    float s0f = (r0 < qlen) ? inv0 : 0.0f;
    float s1f = (r1 < qlen) ? inv1 : 0.0f;
    size_t off0 = base + (size_t)r0 * DD + 2 * q;
    size_t off1 = base + (size_t)r1 * DD + 2 * q;
    #pragma unroll
    for (int ni = 0; ni < 8; ni++) {
        float2 i0 = *(const float2*)(qin + off0 + ni * 8);
        float2 i1 = *(const float2*)(qin + off1 + ni * 8);
        float2 o0 = make_float2(tf32r(i0.x + O[ni][0] * s0f), tf32r(i0.y + O[ni][1] * s0f));
        float2 o1 = make_float2(tf32r(i1.x + O[ni][2] * s1f), tf32r(i1.y + O[ni][3] * s1f));
        *(float2*)(res + off0 + ni * 8) = o0;
        *(float2*)(res + off1 + ni * 8) = o1;
    }
}

// ---------------- kernel 4: mean over T ----------------
__global__ void mean_kernel(const float* __restrict__ x, float* __restrict__ out) {
    int d = blockIdx.x * blockDim.x + threadIdx.x;
    int b = blockIdx.y;
    if (d >= DD) return;
    float s = 0.0f;
    const float* p = x + ((size_t)b * TT) * DD + d;
    for (int t = 0; t < TT; t++) s += p[(size_t)t * DD];
    out[b * DD + d] = s * (1.0f / (float)TT);
}

// ---------------- launch ----------------
extern "C" void kernel_launch(void* const* d_in, const int* in_sizes, int n_in,
                              void* d_out, int out_size) {
    const float* queries = (const float*)d_in[0];
    const float* keys    = (const float*)d_in[1];
    const int*   qlens   = (const int*)d_in[2];
    const int*   klens   = (const int*)d_in[3];
    const float* W_Q     = (const float*)d_in[4];
    const float* W_K     = (const float*)d_in[5];
    const float* W_V     = (const float*)d_in[6];
    const float* fw1     = (const float*)d_in[7];
    const float* fw2     = (const float*)d_in[8];
    float* out = (float*)d_out;

    float *qin, *kin, *qp, *kp, *vp, *resb, *hid, *res2;
    float *wq, *wk, *wv, *f1, *f2;
    cudaGetSymbolAddress((void**)&qin,  g_qin);
    cudaGetSymbolAddress((void**)&kin,  g_kin);
    cudaGetSymbolAddress((void**)&qp,   g_qp);
    cudaGetSymbolAddress((void**)&kp,   g_kp);
    cudaGetSymbolAddress((void**)&vp,   g_vp);
    cudaGetSymbolAddress((void**)&resb, g_res);
    cudaGetSymbolAddress((void**)&hid,  g_hid);
    cudaGetSymbolAddress((void**)&res2, g_res2);
    cudaGetSymbolAddress((void**)&wq,   g_wq);
    cudaGetSymbolAddress((void**)&wk,   g_wk);
    cudaGetSymbolAddress((void**)&wv,   g_wv);
    cudaGetSymbolAddress((void**)&f1,   g_f1);
    cudaGetSymbolAddress((void**)&f2,   g_f2);

    const int M = BB * TT;          // 32768
    const int n_elem = BB * TT * DD;
    const int GEMM_SMEM = 2 * (128 * 36 + 32 * 68) * 4;  // 54272 B

    cudaFuncSetAttribute(tf32_gemm_v6<false, false, true>,
                         cudaFuncAttributeMaxDynamicSharedMemorySize, GEMM_SMEM);
    cudaFuncSetAttribute(tf32_gemm_v6<true, false, true>,
                         cudaFuncAttributeMaxDynamicSharedMemorySize, GEMM_SMEM);
    cudaFuncSetAttribute(tf32_gemm_v6<false, true, false>,
                         cudaFuncAttributeMaxDynamicSharedMemorySize, GEMM_SMEM);

    // 0. round weights to tf32 (one launch)
    roundw_all_kernel<<<(DD * 4 * DD + 255) / 256, 256>>>(
        W_Q, wq, W_K, wk, W_V, wv, fw1, f1, fw2, f2);

    addpe_kernel<<<(n_elem + 255) / 256, 256>>>(queries, keys, qin, kin);

    dim3 gproj(DD / 64, M / 128);
    tf32_gemm_v6<false, false, true><<<gproj, 128, GEMM_SMEM>>>(qin, wq, nullptr, qp, M, DD, DD);
    tf32_gemm_v6<false, false, true><<<gproj, 128, GEMM_SMEM>>>(kin, wk, nullptr, kp, M, DD, DD);
    tf32_gemm_v6<false, false, true><<<gproj, 128, GEMM_SMEM>>>(kp, wv, nullptr, vp, M, DD, DD);

    dim3 gattn(TT / 128, HH, BB);
    attn_mma_kernel<<<gattn, 256>>>(qp, kp, vp, qin, qlens, klens, resb);

    dim3 gff1((4 * DD) / 64, M / 128);
    tf32_gemm_v6<true, false, true><<<gff1, 128, GEMM_SMEM>>>(resb, f1, nullptr, hid, M, 4 * DD, DD);

    dim3 gff2(DD / 64, M / 128);
    tf32_gemm_v6<false, true, false><<<gff2, 128, GEMM_SMEM>>>(hid, f2, resb, res2, M, DD, 4 * DD);

    dim3 gmean(DD / 128, BB);
    mean_kernel<<<gmean, 128>>>(res2, out);
}

// round 14
// speedup vs baseline: 1.0310x; 1.0310x over previous
#include <cuda_runtime.h>
#include <cuda_bf16.h>
#include <math.h>
#include <stdint.h>

// Problem constants
#define BB 64
#define TT 512
#define DD 512
#define HH 8
#define DHH 64

// ---------------- scratch (device globals; allocation-free) ----------------
__device__ float g_qin[BB * TT * DD];
__device__ float g_kin[BB * TT * DD];
__device__ float g_qp [BB * TT * DD];
__device__ float g_kp [BB * TT * DD];
__device__ float g_vp [BB * TT * DD];
__device__ float g_res[BB * TT * DD];
__device__ float g_hid[BB * TT * 4 * DD];
__device__ float g_res2[BB * TT * DD];
// tf32-rounded weight copies
__device__ float g_wq[DD * DD];
__device__ float g_wk[DD * DD];
__device__ float g_wv[DD * DD];
__device__ float g_f1[DD * 4 * DD];
__device__ float g_f2[4 * DD * DD];

__device__ __forceinline__ uint32_t f2tf32(float x) {
    uint32_t r;
    asm("cvt.rna.tf32.f32 %0, %1;" : "=r"(r) : "f"(x));
    return r;
}
__device__ __forceinline__ float tf32r(float x) {
    return __uint_as_float(f2tf32(x));
}

#define CPASYNC16(dst, src) \
    asm volatile("cp.async.cg.shared.global [%0], [%1], 16;" :: "r"(dst), "l"(src))

// ---------------- kernel 0: round all weights to tf32 (single launch) ----------------
__global__ void roundw_all_kernel(const float* __restrict__ wq0, float* __restrict__ wq1,
                                  const float* __restrict__ wk0, float* __restrict__ wk1,
                                  const float* __restrict__ wv0, float* __restrict__ wv1,
                                  const float* __restrict__ f10, float* __restrict__ f11,
                                  const float* __restrict__ f20, float* __restrict__ f21) {
    int i = blockIdx.x * blockDim.x + threadIdx.x;
    if (i < DD * DD) {
        wq1[i] = tf32r(wq0[i]);
        wk1[i] = tf32r(wk0[i]);
        wv1[i] = tf32r(wv0[i]);
    }
    if (i < DD * 4 * DD) {
        f11[i] = tf32r(f10[i]);
        f21[i] = tf32r(f20[i]);
    }
}

// ---------------- kernel 1: positional encoding add (tf32-rounded out) ----------------
__global__ void addpe_kernel(const float* __restrict__ q, const float* __restrict__ k,
                             float* __restrict__ qo, float* __restrict__ ko) {
    int idx = blockIdx.x * blockDim.x + threadIdx.x;
    if (idx >= BB * TT * DD) return;
    int d = idx % DD;
    int t = (idx / DD) % TT;
    int j = (d < DD / 2) ? d : d - DD / 2;
    float invf = expf(-(2.0f * (float)j / (float)DD) * 9.210340371976184f); // ln(10000)
    float arg = (float)t * invf;
    float pe = (d < DD / 2) ? cosf(arg) : sinf(arg);
    qo[idx] = tf32r(q[idx] + pe);
    ko[idx] = tf32r(k[idx] + pe);
}

// ---------------- TF32 GEMM v7: v5 + rotated slices + 2-ahead B prefetch ----------------
// 128x128 block, 64x32 warp tile, 2 CTAs/SM, 3-stage cp.async, 1 barrier/K-tile.
template<bool RELU, bool ADD, bool TFOUT>
__global__ __launch_bounds__(256, 2) void tf32_gemm_v7(
        const float* __restrict__ A, const float* __restrict__ W,
        const float* __restrict__ Src, float* __restrict__ C,
        int M, int N, int K) {
    const int BK = 32;
    const int AST = 36, BST = 136;            // u32 strides; both conflict-free
    const int ASTAGE = 128 * AST, BSTAGE = 32 * BST;
    const int STAGE = ASTAGE + BSTAGE;        // 8960 u32 per stage
    extern __shared__ uint32_t sm[];

    int tid = threadIdx.x;
    int lane = tid & 31, warp = tid >> 5;
    int wr = (warp >> 2) * 64;                // 2 warp-rows
    int wc = (warp & 3) * 32;                 // 4 warp-cols
    int bm = blockIdx.y * 128, bn = blockIdx.x * 128;
    int g = lane >> 2, q = lane & 3;

    uint32_t smem_base = (uint32_t)__cvta_generic_to_shared(sm);

    int lrow = ((lane >> 3) & 1) * 8 + (lane & 7);
    int lcol = (lane >> 4) * 4;
    int sl0 = warp & 3;                       // per-warp slice rotation

    float acc[4][4][4];
    #pragma unroll
    for (int mi = 0; mi < 4; mi++)
        #pragma unroll
        for (int ni = 0; ni < 4; ni++)
            #pragma unroll
            for (int r = 0; r < 4; r++) acc[mi][ni][r] = 0.0f;

    auto stage_load = [&](int k0, int s) {
        uint32_t abase = smem_base + (uint32_t)(s * STAGE) * 4u;
        uint32_t bbase = abase + (uint32_t)ASTAGE * 4u;
        #pragma unroll
        for (int i = 0; i < 4; i++) {
            int c = tid + i * 256;
            int row = c >> 3, col = (c & 7) * 4;
            CPASYNC16(abase + (uint32_t)(row * AST + col) * 4u,
                      A + (size_t)(bm + row) * K + k0 + col);
        }
        #pragma unroll
        for (int i = 0; i < 4; i++) {
            int c = tid + i * 256;
            int kr = c >> 5, col = (c & 31) * 4;
            CPASYNC16(bbase + (uint32_t)(kr * BST + col) * 4u,
                      W + (size_t)(k0 + kr) * N + bn + col);
        }
        asm volatile("cp.async.commit_group;");
    };

    int nk = K / BK;
    stage_load(0, 0);
    stage_load(BK, 1);

    for (int it = 0; it < nk; it++) {
        asm volatile("cp.async.wait_group 1;");
        __syncthreads();   // stage it%3 visible to all; all warps done with it-1
        if (it + 2 < nk) stage_load((it + 2) * BK, (it + 2) % 3);
        else asm volatile("cp.async.commit_group;");

        int s = it % 3;
        uint32_t abuf = smem_base + (uint32_t)(s * STAGE) * 4u;
        const uint32_t* Bb = sm + s * STAGE + ASTAGE;

        // 2-ahead B-fragment prefetch, per-warp rotated slice order
        uint32_t bf[2][4][2];
        #pragma unroll
        for (int ni = 0; ni < 4; ni++) {
            int cn = wc + ni * 8 + g;
            int kkp = sl0 * 8;
            bf[0][ni][0] = Bb[(kkp + q) * BST + cn];
            bf[0][ni][1] = Bb[(kkp + 4 + q) * BST + cn];
            int kkq = ((sl0 + 1) & 3) * 8;
            bf[1][ni][0] = Bb[(kkq + q) * BST + cn];
            bf[1][ni][1] = Bb[(kkq + 4 + q) * BST + cn];
        }

        #pragma unroll
        for (int ks = 0; ks < 4; ks++) {
            int sl = (sl0 + ks) & 3;
            int kk = sl * 8;
            uint32_t af[4][4];
            #pragma unroll
            for (int mi = 0; mi < 4; mi++) {
                uint32_t addr = abuf +
                    (uint32_t)((wr + mi * 16 + lrow) * AST + kk + lcol) * 4u;
                asm volatile(
                    "ldmatrix.sync.aligned.m8n8.x4.shared.b16 {%0,%1,%2,%3}, [%4];"
                    : "=r"(af[mi][0]), "=r"(af[mi][1]),
                      "=r"(af[mi][2]), "=r"(af[mi][3])
                    : "r"(addr));
            }
            int slot = ks & 1;
            #pragma unroll
            for (int mi = 0; mi < 4; mi++)
                #pragma unroll
                for (int ni = 0; ni < 4; ni++) {
                    asm volatile(
                        "mma.sync.aligned.m16n8k8.row.col.f32.tf32.tf32.f32 "
                        "{%0,%1,%2,%3},{%4,%5,%6,%7},{%8,%9},{%0,%1,%2,%3};"
                        : "+f"(acc[mi][ni][0]), "+f"(acc[mi][ni][1]),
                          "+f"(acc[mi][ni][2]), "+f"(acc[mi][ni][3])
                        : "r"(af[mi][0]), "r"(af[mi][1]), "r"(af[mi][2]), "r"(af[mi][3]),
                          "r"(bf[slot][ni][0]), "r"(bf[slot][ni][1]));
                }
            if (ks < 2) {
                int kkn = ((sl0 + ks + 2) & 3) * 8;
                #pragma unroll
                for (int ni = 0; ni < 4; ni++) {
                    int cn = wc + ni * 8 + g;
                    bf[slot][ni][0] = Bb[(kkn + q) * BST + cn];
                    bf[slot][ni][1] = Bb[(kkn + 4 + q) * BST + cn];
                }
            }
        }
    }

    #pragma unroll
    for (int mi = 0; mi < 4; mi++) {
        #pragma unroll
        for (int ni = 0; ni < 4; ni++) {
            int r0 = bm + wr + mi * 16 + g;
            int cn = bn + wc + ni * 8 + 2 * q;
            float v0 = acc[mi][ni][0], v1 = acc[mi][ni][1];
            float v2 = acc[mi][ni][2], v3 = acc[mi][ni][3];
            if (RELU) {
                v0 = fmaxf(v0, 0.0f); v1 = fmaxf(v1, 0.0f);
                v2 = fmaxf(v2, 0.0f); v3 = fmaxf(v3, 0.0f);
            }
            if (ADD) {
                float2 s0 = *(const float2*)(Src + (size_t)r0 * N + cn);
                float2 s1 = *(const float2*)(Src + (size_t)(r0 + 8) * N + cn);
                v0 += s0.x; v1 += s0.y; v2 += s1.x; v3 += s1.y;
            }
            if (TFOUT) {
                v0 = tf32r(v0); v1 = tf32r(v1); v2 = tf32r(v2); v3 = tf32r(v3);
            }
            *(float2*)(C + (size_t)r0 * N + cn)       = make_float2(v0, v1);
            *(float2*)(C + (size_t)(r0 + 8) * N + cn) = make_float2(v2, v3);
        }
    }
}

// ---------------- kernel 3: tf32 flash attention + residual ----------------
#define SC 64
__global__ __launch_bounds__(256) void attn_mma_kernel(
        const float* __restrict__ qp, const float* __restrict__ kp,
        const float* __restrict__ vp, const float* __restrict__ qin,
        const int* __restrict__ qlens, const int* __restrict__ klens,
        float* __restrict__ res) {
    __shared__ uint32_t Ks[SC][68];
    __shared__ uint32_t Vs[SC][72];

    int b = blockIdx.z, h = blockIdx.y;
    int t0 = blockIdx.x * 128;
    int tid = threadIdx.x, lane = tid & 31, warp = tid >> 5;
    int g = lane >> 2, q = lane & 3;
    int klen = klens[b];
    int qlen = qlens[b];
    size_t base = ((size_t)b * TT) * DD + h * DHH;
    int rbase = t0 + warp * 16;

    float O[8][4];
    #pragma unroll
    for (int ni = 0; ni < 8; ni++)
        #pragma unroll
        for (int r = 0; r < 4; r++) O[ni][r] = 0.0f;
    float l0 = 0.0f, l1 = 0.0f;

    if (t0 < qlen) {
        uint32_t aQ[8][4];
        {
            const float* q0 = qp + base + (size_t)(rbase + g) * DD;
            const float* q8 = qp + base + (size_t)(rbase + g + 8) * DD;
            #pragma unroll
            for (int kk = 0; kk < 8; kk++) {
                int c = kk * 8 + q;
                aQ[kk][0] = f2tf32(q0[c] * 0.125f);
                aQ[kk][1] = f2tf32(q8[c] * 0.125f);
                aQ[kk][2] = f2tf32(q0[c + 4] * 0.125f);
                aQ[kk][3] = f2tf32(q8[c + 4] * 0.125f);
            }
        }

        float m0 = -1e30f, m1 = -1e30f;
        int nchunks = (klen + SC - 1) / SC;

        for (int ch = 0; ch < nchunks; ch++) {
            int s0 = ch * SC;
            __syncthreads();
            #pragma unroll
            for (int i = 0; i < 4; i++) {
                int c = tid + i * 256;
                int row = c >> 4;
                int col = (c & 15) * 4;
                size_t off = base + (size_t)(s0 + row) * DD + col;
                float4 kv4 = *(const float4*)(kp + off);
                Ks[row][col + 0] = __float_as_uint(kv4.x);
                Ks[row][col + 1] = __float_as_uint(kv4.y);
                Ks[row][col + 2] = __float_as_uint(kv4.z);
                Ks[row][col + 3] = __float_as_uint(kv4.w);
                float4 vv4 = *(const float4*)(vp + off);
                Vs[row][col + 0] = __float_as_uint(vv4.x);
                Vs[row][col + 1] = __float_as_uint(vv4.y);
                Vs[row][col + 2] = __float_as_uint(vv4.z);
                Vs[row][col + 3] = __float_as_uint(vv4.w);
            }
            __syncthreads();

            float sacc[8][4];
            #pragma unroll
            for (int ni = 0; ni < 8; ni++)
                #pragma unroll
                for (int r = 0; r < 4; r++) sacc[ni][r] = 0.0f;
            #pragma unroll
            for (int kk = 0; kk < 8; kk++) {
                #pragma unroll
                for (int ni = 0; ni < 8; ni++) {
                    uint32_t b0 = Ks[ni * 8 + g][kk * 8 + q];
                    uint32_t b1 = Ks[ni * 8 + g][kk * 8 + q + 4];
                    asm volatile(
                        "mma.sync.aligned.m16n8k8.row.col.f32.tf32.tf32.f32 "
                        "{%0,%1,%2,%3},{%4,%5,%6,%7},{%8,%9},{%0,%1,%2,%3};"
                        : "+f"(sacc[ni][0]), "+f"(sacc[ni][1]),
                          "+f"(sacc[ni][2]), "+f"(sacc[ni][3])
                        : "r"(aQ[kk][0]), "r"(aQ[kk][1]), "r"(aQ[kk][2]), "r"(aQ[kk][3]),
                          "r"(b0), "r"(b1));
                }
            }

            int cb = s0 + 2 * q;
            #pragma unroll
            for (int ni = 0; ni < 8; ni++) {
                if (cb + ni * 8     >= klen) { sacc[ni][0] = -1e30f; sacc[ni][2] = -1e30f; }
                if (cb + ni * 8 + 1 >= klen) { sacc[ni][1] = -1e30f; sacc[ni][3] = -1e30f; }
            }

            float mc0 = -1e30f, mc1 = -1e30f;
            #pragma unroll
            for (int ni = 0; ni < 8; ni++) {
                mc0 = fmaxf(mc0, fmaxf(sacc[ni][0], sacc[ni][1]));
                mc1 = fmaxf(mc1, fmaxf(sacc[ni][2], sacc[ni][3]));
            }
            #pragma unroll
            for (int o = 1; o <= 2; o <<= 1) {
                mc0 = fmaxf(mc0, __shfl_xor_sync(0xffffffffu, mc0, o));
                mc1 = fmaxf(mc1, __shfl_xor_sync(0xffffffffu, mc1, o));
            }
            float mn0 = fmaxf(m0, mc0), mn1 = fmaxf(m1, mc1);
            float al0 = __expf(m0 - mn0), al1 = __expf(m1 - mn1);
            m0 = mn0; m1 = mn1;

            float rs0 = 0.0f, rs1 = 0.0f;
            #pragma unroll
            for (int ni = 0; ni < 8; ni++) {
                float p0 = __expf(sacc[ni][0] - m0);
                float p1 = __expf(sacc[ni][1] - m0);
                float p2 = __expf(sacc[ni][2] - m1);
                float p3 = __expf(sacc[ni][3] - m1);
                rs0 += p0 + p1; rs1 += p2 + p3;
                sacc[ni][0] = p0; sacc[ni][1] = p1; sacc[ni][2] = p2; sacc[ni][3] = p3;
            }
            #pragma unroll
            for (int o = 1; o <= 2; o <<= 1) {
                rs0 += __shfl_xor_sync(0xffffffffu, rs0, o);
                rs1 += __shfl_xor_sync(0xffffffffu, rs1, o);
            }
            l0 = l0 * al0 + rs0;
            l1 = l1 * al1 + rs1;
            #pragma unroll
            for (int ni = 0; ni < 8; ni++) {
                O[ni][0] *= al0; O[ni][1] *= al0;
                O[ni][2] *= al1; O[ni][3] *= al1;
            }

            int srcA = g * 4 + (q >> 1);
            int srcB = srcA + 2;
            bool odd = (q & 1);
            #pragma unroll
            for (int ks = 0; ks < 8; ks++) {
                float v00 = __shfl_sync(0xffffffffu, sacc[ks][0], srcA);
                float v01 = __shfl_sync(0xffffffffu, sacc[ks][1], srcA);
                float v10 = __shfl_sync(0xffffffffu, sacc[ks][2], srcA);
                float v11 = __shfl_sync(0xffffffffu, sacc[ks][3], srcA);
                float w00 = __shfl_sync(0xffffffffu, sacc[ks][0], srcB);
                float w01 = __shfl_sync(0xffffffffu, sacc[ks][1], srcB);
                float w10 = __shfl_sync(0xffffffffu, sacc[ks][2], srcB);
                float w11 = __shfl_sync(0xffffffffu, sacc[ks][3], srcB);
                uint32_t a0 = f2tf32(odd ? v01 : v00);
                uint32_t a1 = f2tf32(odd ? v11 : v10);
                uint32_t a2 = f2tf32(odd ? w01 : w00);
                uint32_t a3 = f2tf32(odd ? w11 : w10);
                #pragma unroll
                for (int ni = 0; ni < 8; ni++) {
                    uint32_t b0 = Vs[ks * 8 + q    ][ni * 8 + g];
                    uint32_t b1 = Vs[ks * 8 + q + 4][ni * 8 + g];
                    asm volatile(
                        "mma.sync.aligned.m16n8k8.row.col.f32.tf32.tf32.f32 "
                        "{%0,%1,%2,%3},{%4,%5,%6,%7},{%8,%9},{%0,%1,%2,%3};"
                        : "+f"(O[ni][0]), "+f"(O[ni][1]),
                          "+f"(O[ni][2]), "+f"(O[ni][3])
                        : "r"(a0), "r"(a1), "r"(a2), "r"(a3),
                          "r"(b0), "r"(b1));
                }
            }
        }
    }

    float inv0 = (l0 > 0.0f) ? 1.0f / l0 : 0.0f;
    float inv1 = (l1 > 0.0f) ? 1.0f / l1 : 0.0f;
    int r0 = rbase + g, r1 = rbase + g + 8;
    float s0f = (r0 < qlen) ? inv0 : 0.0f;
    float s1f = (r1 < qlen) ? inv1 : 0.0f;
    size_t off0 = base + (size_t)r0 * DD + 2 * q;
    size_t off1 = base + (size_t)r1 * DD + 2 * q;
    #pragma unroll
    for (int ni = 0; ni < 8; ni++) {
        float2 i0 = *(const float2*)(qin + off0 + ni * 8);
        float2 i1 = *(const float2*)(qin + off1 + ni * 8);
        float2 o0 = make_float2(tf32r(i0.x + O[ni][0] * s0f), tf32r(i0.y + O[ni][1] * s0f));
        float2 o1 = make_float2(tf32r(i1.x + O[ni][2] * s1f), tf32r(i1.y + O[ni][3] * s1f));
        *(float2*)(res + off0 + ni * 8) = o0;
        *(float2*)(res + off1 + ni * 8) = o1;
    }
}

// ---------------- kernel 4: mean over T ----------------
__global__ void mean_kernel(const float* __restrict__ x, float* __restrict__ out) {
    int d = blockIdx.x * blockDim.x + threadIdx.x;
    int b = blockIdx.y;
    if (d >= DD) return;
    float s = 0.0f;
    const float* p = x + ((size_t)b * TT) * DD + d;
    for (int t = 0; t < TT; t++) s += p[(size_t)t * DD];
    out[b * DD + d] = s * (1.0f / (float)TT);
}

// ---------------- launch ----------------
extern "C" void kernel_launch(void* const* d_in, const int* in_sizes, int n_in,
                              void* d_out, int out_size) {
    const float* queries = (const float*)d_in[0];
    const float* keys    = (const float*)d_in[1];
    const int*   qlens   = (const int*)d_in[2];
    const int*   klens   = (const int*)d_in[3];
    const float* W_Q     = (const float*)d_in[4];
    const float* W_K     = (const float*)d_in[5];
    const float* W_V     = (const float*)d_in[6];
    const float* fw1     = (const float*)d_in[7];
    const float* fw2     = (const float*)d_in[8];
    float* out = (float*)d_out;

    float *qin, *kin, *qp, *kp, *vp, *resb, *hid, *res2;
    float *wq, *wk, *wv, *f1, *f2;
    cudaGetSymbolAddress((void**)&qin,  g_qin);
    cudaGetSymbolAddress((void**)&kin,  g_kin);
    cudaGetSymbolAddress((void**)&qp,   g_qp);
    cudaGetSymbolAddress((void**)&kp,   g_kp);
    cudaGetSymbolAddress((void**)&vp,   g_vp);
    cudaGetSymbolAddress((void**)&resb, g_res);
    cudaGetSymbolAddress((void**)&hid,  g_hid);
    cudaGetSymbolAddress((void**)&res2, g_res2);
    cudaGetSymbolAddress((void**)&wq,   g_wq);
    cudaGetSymbolAddress((void**)&wk,   g_wk);
    cudaGetSymbolAddress((void**)&wv,   g_wv);
    cudaGetSymbolAddress((void**)&f1,   g_f1);
    cudaGetSymbolAddress((void**)&f2,   g_f2);

    const int M = BB * TT;          // 32768
    const int n_elem = BB * TT * DD;
    const int GEMM_SMEM = 3 * (128 * 36 + 32 * 136) * 4;  // 107520 B

    cudaFuncSetAttribute(tf32_gemm_v7<false, false, true>,
                         cudaFuncAttributeMaxDynamicSharedMemorySize, GEMM_SMEM);
    cudaFuncSetAttribute(tf32_gemm_v7<true, false, true>,
                         cudaFuncAttributeMaxDynamicSharedMemorySize, GEMM_SMEM);
    cudaFuncSetAttribute(tf32_gemm_v7<false, true, false>,
                         cudaFuncAttributeMaxDynamicSharedMemorySize, GEMM_SMEM);

    // 0. round weights to tf32 (one launch)
    roundw_all_kernel<<<(DD * 4 * DD + 255) / 256, 256>>>(
        W_Q, wq, W_K, wk, W_V, wv, fw1, f1, fw2, f2);

    addpe_kernel<<<(n_elem + 255) / 256, 256>>>(queries, keys, qin, kin);

    dim3 gproj(DD / 128, M / 128);
    tf32_gemm_v7<false, false, true><<<gproj, 256, GEMM_SMEM>>>(qin, wq, nullptr, qp, M, DD, DD);
    tf32_gemm_v7<false, false, true><<<gproj, 256, GEMM_SMEM>>>(kin, wk, nullptr, kp, M, DD, DD);
    tf32_gemm_v7<false, false, true><<<gproj, 256, GEMM_SMEM>>>(kp, wv, nullptr, vp, M, DD, DD);

    dim3 gattn(TT / 128, HH, BB);
    attn_mma_kernel<<<gattn, 256>>>(qp, kp, vp, qin, qlens, klens, resb);

    dim3 gff1((4 * DD) / 128, M / 128);
    tf32_gemm_v7<true, false, true><<<gff1, 256, GEMM_SMEM>>>(resb, f1, nullptr, hid, M, 4 * DD, DD);

    dim3 gff2(DD / 128, M / 128);
    tf32_gemm_v7<false, true, false><<<gff2, 256, GEMM_SMEM>>>(hid, f2, resb, res2, M, DD, 4 * DD);

    dim3 gmean(DD / 128, BB);
    mean_kernel<<<gmean, 128>>>(res2, out);
}